// round 9
// baseline (speedup 1.0000x reference)
#include <cuda_runtime.h>

#define HW (2048*2048)
#define SRADII_MAX 589824   // 768^2
#define SCLEAN_MAX 586756   // 766^2
#define RGATE2     585225   // 765^2 : only px with d2>=this can be scatter targets (768 - 2*sqrt(2) = 765.17)

// 32-bit packed winner: (order+1)<<5 | (dh+2)<<3 | (dw+2)<<1 | neg
// src = p + (neg ? -1 : +1) * (dh*2048 + dw).  order+1 <= 16728100 < 2^24, so value < 2^29.
__device__ unsigned int g_packed[HW];

// Gaussian sigma=2, truncate=4 -> radius 8 ; weight for tap offset o is c_w[|o|]
__constant__ float c_w[9] = {
    0.19947464f, 0.17603575f, 0.12098747f, 0.06475993f,
    0.02699595f, 0.00876430f, 0.00221596f, 0.00043635f, 0.00006692f
};

__device__ __forceinline__ float wtap(int k) {   // k in [0,16], offset k-8
    return c_w[k < 8 ? 8 - k : k - 8];
}

// ---------------------------------------------------------------- scatter
__global__ void k_scatter(const int2* __restrict__ off) {
    int w = blockIdx.x * blockDim.x + threadIdx.x;
    int h = blockIdx.y;
    if (w >= 2045) return;
    int hh = h + 2, ww = w + 2;
    int dx = 1024 - ww, dy = 1024 - hh;
    if (dx*dx + dy*dy < SRADII_MAX) return;

    int lin   = hh * 2048 + ww;
    int local = h * 2045 + w;
    #pragma unroll
    for (int i = 0; i < 2; i++) {
        int2 o = off[i * (2045*2045) + local];           // (dh, dw), each in [-2,1]
        int lin2 = lin + o.x * 2048 + o.y;
        unsigned o1p1 = (unsigned)(i * 2 * (2045*2045) + 2*local + 1);  // order1 + 1
        unsigned base = (o1p1 << 5) | ((unsigned)(o.x + 2) << 3) | ((unsigned)(o.y + 2) << 1);
        atomicMax(&g_packed[lin],  base);            // tgt=lin : src = lin + D  (neg=0)
        atomicMax(&g_packed[lin2], base + 32u + 1u); // tgt=lin2: src = lin2 - D (order2=order1+1, neg=1)
    }
}

// ---------------------------------------------------------------- fused gather + H blur (in-place) + V blur + finalize
// grid (32, 128), block 256. Output tile 64x16, halo 80x32 in smem (3 channels).
__global__ __launch_bounds__(256) void k_fused(const float* __restrict__ img,
                                               float* __restrict__ out) {
    int x0 = blockIdx.x << 6;
    int y0 = blockIdx.y << 4;
    int tid = threadIdx.x;

    int dxa = 1024 - x0, dxb = 1024 - (x0 + 63);
    int maxdx2 = max(dxa*dxa, dxb*dxb);
    int mindx2 = (x0 <= 1024 && 1024 <= x0 + 63) ? 0 : min(dxa*dxa, dxb*dxb);
    int dya = 1024 - y0, dyb = 1024 - (y0 + 15);
    int maxdy2 = max(dya*dya, dyb*dyb);
    int mindy2 = (y0 <= 1024 && 1024 <= y0 + 15) ? 0 : min(dya*dya, dyb*dyb);

    if (maxdx2 + maxdy2 < SCLEAN_MAX) {       // whole tile clean: pure float4 copy
        int fb = ((y0 * 2048 + x0) * 3) >> 2;
        const float4* s = (const float4*)img;
        float4*       d = (float4*)out;
        #pragma unroll
        for (int i = 0; i < 3; i++) {
            int j  = tid + (i << 8);
            int row = j / 48, col = j - row * 48;
            int fi = fb + row * 1536 + col;
            d[fi] = s[fi];
        }
        return;
    }

    __shared__ float s_in[3][32][80];         // gathered /255; H result written back in-place to cols [8,72)

    // ---- load + inline gather (2560 halo pixels, 10 per thread) ----
    const float inv = 1.0f / 255.0f;
    #pragma unroll
    for (int it = 0; it < 10; it++) {
        int i  = tid + (it << 8);
        int hy = i / 80, hx = i - hy * 80;
        int gy = y0 - 8 + hy; gy = gy < 0 ? 0 : (gy > 2047 ? 2047 : gy);
        int gx = x0 - 8 + hx; gx = gx < 0 ? 0 : (gx > 2047 ? 2047 : gx);
        int p  = gy * 2048 + gx;
        int src = p;
        int ddx = 1024 - gx, ddy = 1024 - gy;
        if (ddx*ddx + ddy*ddy >= RGATE2) {
            unsigned v = g_packed[p];
            if (v) {
                int D = (((int)((v >> 3) & 3u)) - 2) * 2048 + (((int)((v >> 1) & 3u)) - 2);
                src = (v & 1u) ? p - D : p + D;
            }
        }
        s_in[0][hy][hx] = img[src*3 + 0] * inv;
        s_in[1][hy][hx] = img[src*3 + 1] * inv;
        s_in[2][hy][hx] = img[src*3 + 2] * inv;
    }
    __syncthreads();

    int yy  = tid >> 3;                       // H pass: row 0..31
    int xb  = (tid & 7) << 3;                 // H pass: col block 0,8,..,56

    // ---- H blur, in place: read 24, sync, write 8 back at col offset +8 ----
    #pragma unroll
    for (int c = 0; c < 3; c++) {
        float v[24];
        const float4* rp = (const float4*)&s_in[c][yy][xb];
        #pragma unroll
        for (int q = 0; q < 6; q++) {
            float4 t = rp[q];
            v[4*q] = t.x; v[4*q+1] = t.y; v[4*q+2] = t.z; v[4*q+3] = t.w;
        }
        __syncthreads();                      // all reads of plane c done before overwrites
        float ho[8];
        #pragma unroll
        for (int j = 0; j < 8; j++) {
            float a = 0.0f;
            #pragma unroll
            for (int k = 0; k < 17; k++) a += wtap(k) * v[j + k];
            ho[j] = a;
        }
        *(float4*)&s_in[c][yy][8 + xb]     = make_float4(ho[0], ho[1], ho[2], ho[3]);
        *(float4*)&s_in[c][yy][12 + xb]    = make_float4(ho[4], ho[5], ho[6], ho[7]);
    }
    __syncthreads();

    // ---- V blur, all channels: thread = (column, 4-row group) ----
    bool mixed = (mindx2 + mindy2) < SCLEAN_MAX;
    int xo  = tid & 63;
    int grp = tid >> 6;
    int px  = x0 + xo;
    int dxp2 = (1024 - px) * (1024 - px);

    float acc[3][4];
    #pragma unroll
    for (int c = 0; c < 3; c++)
        #pragma unroll
        for (int r = 0; r < 4; r++) acc[c][r] = 0.0f;

    #pragma unroll
    for (int k = 0; k < 20; k++) {
        int row = (grp << 2) + k;
        #pragma unroll
        for (int c = 0; c < 3; c++) {
            float val = s_in[c][row][8 + xo];
            if (k <= 16)           acc[c][0] += wtap(k)     * val;
            if (k >= 1 && k <= 17) acc[c][1] += wtap(k - 1) * val;
            if (k >= 2 && k <= 18) acc[c][2] += wtap(k - 2) * val;
            if (k >= 3)            acc[c][3] += wtap(k - 3) * val;
        }
    }

    #pragma unroll
    for (int r = 0; r < 4; r++) {
        int y  = y0 + (grp << 2) + r;
        int bi = (y * 2048 + px) * 3;
        float r0 = fminf(fmaxf(acc[0][r], 0.0f), 1.0f) * 255.0f;
        float r1 = fminf(fmaxf(acc[1][r], 0.0f), 1.0f) * 255.0f;
        float r2 = fminf(fmaxf(acc[2][r], 0.0f), 1.0f) * 255.0f;
        if (mixed) {
            int dyp = 1024 - y;
            if (dxp2 + dyp * dyp < SCLEAN_MAX) {
                r0 = img[bi]; r1 = img[bi + 1]; r2 = img[bi + 2];
            }
        }
        out[bi]     = r0;
        out[bi + 1] = r1;
        out[bi + 2] = r2;
    }
}

extern "C" void kernel_launch(void* const* d_in, const int* in_sizes, int n_in,
                              void* d_out, int out_size) {
    const float* img;
    const int*   off;
    if (in_sizes[0] == 2048*2048*3) {
        img = (const float*)d_in[0];
        off = (const int*)d_in[1];
    } else {
        img = (const float*)d_in[1];
        off = (const int*)d_in[0];
    }
    float* out = (float*)d_out;

    void* pk = nullptr;
    cudaGetSymbolAddress(&pk, g_packed);
    cudaMemsetAsync(pk, 0, sizeof(unsigned int) * HW, 0);

    dim3 sg((2045 + 255) / 256, 2045);
    k_scatter<<<sg, 256>>>((const int2*)off);

    k_fused<<<dim3(32, 128), 256>>>(img, out);
}

// round 10
// speedup vs baseline: 1.6136x; 1.6136x over previous
#include <cuda_runtime.h>

#define HW (2048*2048)
#define SRADII_MAX 589824   // 768^2
#define SCLEAN_MAX 586756   // 766^2
#define RGATE2     585225   // 765^2 : only px with d2>=this can be scatter targets

// 32-bit packed winner: (order+1)<<5 | (dh+2)<<3 | (dw+2)<<1 | neg
// src = p + (neg ? -1 : +1) * (dh*2048 + dw).  order+1 <= 16728100 < 2^24, value < 2^29.
__device__ unsigned int g_packed[HW];

// Gaussian sigma=2, truncate=4 -> radius 8 ; weight for tap offset o is c_w[|o|]
__constant__ float c_w[9] = {
    0.19947464f, 0.17603575f, 0.12098747f, 0.06475993f,
    0.02699595f, 0.00876430f, 0.00221596f, 0.00043635f, 0.00006692f
};

__device__ __forceinline__ float wtap(int k) {   // k in [0,16], offset k-8
    return c_w[k < 8 ? 8 - k : k - 8];
}

// ---------------------------------------------------------------- scatter
__global__ void k_scatter(const int2* __restrict__ off) {
    int w = blockIdx.x * blockDim.x + threadIdx.x;
    int h = blockIdx.y;
    if (w >= 2045) return;
    int hh = h + 2, ww = w + 2;
    int dx = 1024 - ww, dy = 1024 - hh;
    if (dx*dx + dy*dy < SRADII_MAX) return;

    int lin   = hh * 2048 + ww;
    int local = h * 2045 + w;
    #pragma unroll
    for (int i = 0; i < 2; i++) {
        int2 o = off[i * (2045*2045) + local];           // (dh, dw), each in [-2,1]
        int lin2 = lin + o.x * 2048 + o.y;
        unsigned o1p1 = (unsigned)(i * 2 * (2045*2045) + 2*local + 1);  // order1 + 1
        unsigned base = (o1p1 << 5) | ((unsigned)(o.x + 2) << 3) | ((unsigned)(o.y + 2) << 1);
        atomicMax(&g_packed[lin],  base);            // tgt=lin : src = lin + D  (neg=0)
        atomicMax(&g_packed[lin2], base + 32u + 1u); // tgt=lin2: src = lin2 - D (neg=1)
    }
}

// ---------------------------------------------------------------- fused gather + H blur + V blur + finalize
// R8 structure (separate s_h, no in-place overwrite -> no spills), 32-bit packed decode.
// grid (32, 128), block 256. Output tile 64x16, halo 80x32 in smem.
__global__ __launch_bounds__(256) void k_fused(const float* __restrict__ img,
                                               float* __restrict__ out) {
    int x0 = blockIdx.x << 6;
    int y0 = blockIdx.y << 4;
    int tid = threadIdx.x;

    int dxa = 1024 - x0, dxb = 1024 - (x0 + 63);
    int maxdx2 = max(dxa*dxa, dxb*dxb);
    int mindx2 = (x0 <= 1024 && 1024 <= x0 + 63) ? 0 : min(dxa*dxa, dxb*dxb);
    int dya = 1024 - y0, dyb = 1024 - (y0 + 15);
    int maxdy2 = max(dya*dya, dyb*dyb);
    int mindy2 = (y0 <= 1024 && 1024 <= y0 + 15) ? 0 : min(dya*dya, dyb*dyb);

    if (maxdx2 + maxdy2 < SCLEAN_MAX) {       // whole tile clean: pure float4 copy
        int fb = ((y0 * 2048 + x0) * 3) >> 2;
        const float4* s = (const float4*)img;
        float4*       d = (float4*)out;
        #pragma unroll
        for (int i = 0; i < 3; i++) {
            int j  = tid + (i << 8);
            int row = j / 48, col = j - row * 48;
            int fi = fb + row * 1536 + col;
            d[fi] = s[fi];
        }
        return;
    }

    __shared__ float s_in[3][32][80];         // gathered /255, halo tile
    __shared__ float s_h[32][64];             // H-blur result, one channel at a time

    // ---- load + inline gather (2560 halo pixels, 10 per thread) ----
    const float inv = 1.0f / 255.0f;
    #pragma unroll
    for (int it = 0; it < 10; it++) {
        int i  = tid + (it << 8);
        int hy = i / 80, hx = i - hy * 80;
        int gy = y0 - 8 + hy; gy = gy < 0 ? 0 : (gy > 2047 ? 2047 : gy);
        int gx = x0 - 8 + hx; gx = gx < 0 ? 0 : (gx > 2047 ? 2047 : gx);
        int p  = gy * 2048 + gx;
        int src = p;
        int ddx = 1024 - gx, ddy = 1024 - gy;
        if (ddx*ddx + ddy*ddy >= RGATE2) {
            unsigned v = g_packed[p];
            if (v) {
                int D = (((int)((v >> 3) & 3u)) - 2) * 2048 + (((int)((v >> 1) & 3u)) - 2);
                src = (v & 1u) ? p - D : p + D;
            }
        }
        s_in[0][hy][hx] = img[src*3 + 0] * inv;
        s_in[1][hy][hx] = img[src*3 + 1] * inv;
        s_in[2][hy][hx] = img[src*3 + 2] * inv;
    }
    __syncthreads();

    bool mixed = (mindx2 + mindy2) < SCLEAN_MAX;
    int yy  = tid >> 3;                       // H pass: row 0..31
    int xb  = (tid & 7) << 3;                 // H pass: col block 0,8,..,56
    int xo  = tid & 63;                       // V pass: column
    int grp = tid >> 6;                       // V pass: 4-row group 0..3
    int px  = x0 + xo;
    int dxp2 = (1024 - px) * (1024 - px);

    #pragma unroll
    for (int c = 0; c < 3; c++) {
        // ---- H blur: 8 outputs from 24 inputs (6 x LDS.128) ----
        float v[24];
        const float4* rp = (const float4*)&s_in[c][yy][xb];
        #pragma unroll
        for (int q = 0; q < 6; q++) {
            float4 t = rp[q];
            v[4*q] = t.x; v[4*q+1] = t.y; v[4*q+2] = t.z; v[4*q+3] = t.w;
        }
        float ho[8];
        #pragma unroll
        for (int j = 0; j < 8; j++) {
            float a = 0.0f;
            #pragma unroll
            for (int k = 0; k < 17; k++) a += wtap(k) * v[j + k];
            ho[j] = a;
        }
        *(float4*)&s_h[yy][xb]     = make_float4(ho[0], ho[1], ho[2], ho[3]);
        *(float4*)&s_h[yy][xb + 4] = make_float4(ho[4], ho[5], ho[6], ho[7]);
        __syncthreads();

        // ---- V blur: stream 20 rows, accumulate 4 output rows ----
        float a0 = 0.f, a1 = 0.f, a2 = 0.f, a3 = 0.f;
        #pragma unroll
        for (int k = 0; k < 20; k++) {
            float val = s_h[(grp << 2) + k][xo];
            if (k <= 16)           a0 += wtap(k)     * val;
            if (k >= 1 && k <= 17) a1 += wtap(k - 1) * val;
            if (k >= 2 && k <= 18) a2 += wtap(k - 2) * val;
            if (k >= 3)            a3 += wtap(k - 3) * val;
        }
        float accs[4] = {a0, a1, a2, a3};
        #pragma unroll
        for (int r = 0; r < 4; r++) {
            int y  = y0 + (grp << 2) + r;
            int oi = (y * 2048 + px) * 3 + c;
            float bv = fminf(fmaxf(accs[r], 0.0f), 1.0f) * 255.0f;
            if (mixed) {
                int dyp = 1024 - y;
                if (dxp2 + dyp * dyp < SCLEAN_MAX) bv = img[oi];
            }
            out[oi] = bv;
        }
        __syncthreads();                      // s_h reused by next channel
    }
}

extern "C" void kernel_launch(void* const* d_in, const int* in_sizes, int n_in,
                              void* d_out, int out_size) {
    const float* img;
    const int*   off;
    if (in_sizes[0] == 2048*2048*3) {
        img = (const float*)d_in[0];
        off = (const int*)d_in[1];
    } else {
        img = (const float*)d_in[1];
        off = (const int*)d_in[0];
    }
    float* out = (float*)d_out;

    void* pk = nullptr;
    cudaGetSymbolAddress(&pk, g_packed);
    cudaMemsetAsync(pk, 0, sizeof(unsigned int) * HW, 0);

    dim3 sg((2045 + 255) / 256, 2045);
    k_scatter<<<sg, 256>>>((const int2*)off);

    k_fused<<<dim3(32, 128), 256>>>(img, out);
}

// round 11
// speedup vs baseline: 1.7426x; 1.0800x over previous
#include <cuda_runtime.h>
#include <cuda_fp16.h>

#define HW (2048*2048)
#define SRADII_MAX 589824   // 768^2
#define SCLEAN_MAX 586756   // 766^2
#define RGATE2     585225   // 765^2 : only px with d2>=this can be scatter targets

// 32-bit packed winner: (order+1)<<5 | (dh+2)<<3 | (dw+2)<<1 | neg
// src = p + (neg ? -1 : +1) * (dh*2048 + dw).
__device__ unsigned int g_packed[HW];

// Gaussian sigma=2, truncate=4 -> radius 8 ; weight for tap offset o is c_w[|o|]
__constant__ float c_w[9] = {
    0.19947464f, 0.17603575f, 0.12098747f, 0.06475993f,
    0.02699595f, 0.00876430f, 0.00221596f, 0.00043635f, 0.00006692f
};

__device__ __forceinline__ float wtap(int k) {   // k in [0,16], offset k-8
    return c_w[k < 8 ? 8 - k : k - 8];
}

// ---------------------------------------------------------------- scatter
__global__ void k_scatter(const int2* __restrict__ off) {
    int w = blockIdx.x * blockDim.x + threadIdx.x;
    int h = blockIdx.y;
    if (w >= 2045) return;
    int hh = h + 2, ww = w + 2;
    int dx = 1024 - ww, dy = 1024 - hh;
    if (dx*dx + dy*dy < SRADII_MAX) return;

    int lin   = hh * 2048 + ww;
    int local = h * 2045 + w;

    // i = 0 : its write to lin is dominated by i=1's write to lin (higher order),
    // so only the lin2 atomic is needed.
    {
        int2 o = off[local];
        int lin2 = lin + o.x * 2048 + o.y;
        unsigned o1p1 = (unsigned)(2*local + 1);
        unsigned base = (o1p1 << 5) | ((unsigned)(o.x + 2) << 3) | ((unsigned)(o.y + 2) << 1);
        atomicMax(&g_packed[lin2], base + 32u + 1u);   // src = lin2 - D
    }
    // i = 1 : both writes
    {
        int2 o = off[(2045*2045) + local];
        int lin2 = lin + o.x * 2048 + o.y;
        unsigned o1p1 = (unsigned)(2 * (2045*2045) + 2*local + 1);
        unsigned base = (o1p1 << 5) | ((unsigned)(o.x + 2) << 3) | ((unsigned)(o.y + 2) << 1);
        atomicMax(&g_packed[lin],  base);
        atomicMax(&g_packed[lin2], base + 32u + 1u);
    }
}

// ---------------------------------------------------------------- fused gather + H blur + V blur + finalize
// grid (32, 128), block 256. Output tile 64x16, halo 80x32.
// fp16 smem intermediates, fp32 arithmetic. V pass: thread = (column, channel), 16 rows each.
__global__ __launch_bounds__(256, 5) void k_fused(const float* __restrict__ img,
                                                  float* __restrict__ out) {
    int x0 = blockIdx.x << 6;
    int y0 = blockIdx.y << 4;
    int tid = threadIdx.x;

    int dxa = 1024 - x0, dxb = 1024 - (x0 + 63);
    int maxdx2 = max(dxa*dxa, dxb*dxb);
    int mindx2 = (x0 <= 1024 && 1024 <= x0 + 63) ? 0 : min(dxa*dxa, dxb*dxb);
    int dya = 1024 - y0, dyb = 1024 - (y0 + 15);
    int maxdy2 = max(dya*dya, dyb*dyb);
    int mindy2 = (y0 <= 1024 && 1024 <= y0 + 15) ? 0 : min(dya*dya, dyb*dyb);

    if (maxdx2 + maxdy2 < SCLEAN_MAX) {       // whole tile clean: pure float4 copy
        int fb = ((y0 * 2048 + x0) * 3) >> 2;
        const float4* s = (const float4*)img;
        float4*       d = (float4*)out;
        #pragma unroll
        for (int i = 0; i < 3; i++) {
            int j  = tid + (i << 8);
            int row = j / 48, col = j - row * 48;
            int fi = fb + row * 1536 + col;
            d[fi] = s[fi];
        }
        return;
    }

    __shared__ __half s_in[3][32][88];        // gathered /255 (80 valid cols; 88 = 16B-aligned rows)
    __shared__ __half s_h[3][32][66];         // H-blur result (64 valid; 66 rotates banks)

    // ---- load + inline gather (2560 halo pixels, 10 per thread) ----
    const float inv = 1.0f / 255.0f;
    #pragma unroll
    for (int it = 0; it < 10; it++) {
        int i  = tid + (it << 8);
        int hy = i / 80, hx = i - hy * 80;
        int gy = y0 - 8 + hy; gy = gy < 0 ? 0 : (gy > 2047 ? 2047 : gy);
        int gx = x0 - 8 + hx; gx = gx < 0 ? 0 : (gx > 2047 ? 2047 : gx);
        int p  = gy * 2048 + gx;
        int src = p;
        int ddx = 1024 - gx, ddy = 1024 - gy;
        if (ddx*ddx + ddy*ddy >= RGATE2) {
            unsigned v = g_packed[p];
            if (v) {
                int D = (((int)((v >> 3) & 3u)) - 2) * 2048 + (((int)((v >> 1) & 3u)) - 2);
                src = (v & 1u) ? p - D : p + D;
            }
        }
        s_in[0][hy][hx] = __float2half_rn(img[src*3 + 0] * inv);
        s_in[1][hy][hx] = __float2half_rn(img[src*3 + 1] * inv);
        s_in[2][hy][hx] = __float2half_rn(img[src*3 + 2] * inv);
    }
    __syncthreads();

    // ---- H blur: thread = (row yy, col-block xb), 8 outputs per channel ----
    {
        int yy = tid >> 3;
        int xb = (tid & 7) << 3;
        #pragma unroll
        for (int c = 0; c < 3; c++) {
            float v[24];
            const uint4* up = reinterpret_cast<const uint4*>(&s_in[c][yy][xb]);
            #pragma unroll
            for (int q = 0; q < 3; q++) {
                uint4 u = up[q];
                unsigned uw[4] = {u.x, u.y, u.z, u.w};
                #pragma unroll
                for (int m = 0; m < 4; m++) {
                    float2 f = __half22float2(*reinterpret_cast<__half2*>(&uw[m]));
                    v[8*q + 2*m]     = f.x;
                    v[8*q + 2*m + 1] = f.y;
                }
            }
            float ho[8];
            #pragma unroll
            for (int j = 0; j < 8; j++) {
                float a = 0.0f;
                #pragma unroll
                for (int k = 0; k < 17; k++) a += wtap(k) * v[j + k];
                ho[j] = a;
            }
            #pragma unroll
            for (int q = 0; q < 4; q++)
                *reinterpret_cast<__half2*>(&s_h[c][yy][xb + 2*q]) =
                    __floats2half2_rn(ho[2*q], ho[2*q + 1]);
        }
    }
    __syncthreads();

    // ---- V blur: thread = (column, channel); 32 input rows -> 16 output rows ----
    if (tid < 192) {
        int col = tid & 63;
        int ch  = tid >> 6;
        int px  = x0 + col;
        int dxp2 = (1024 - px) * (1024 - px);
        bool mixed = (mindx2 + mindy2) < SCLEAN_MAX;

        float acc[16];
        #pragma unroll
        for (int r = 0; r < 16; r++) acc[r] = 0.0f;

        #pragma unroll
        for (int k = 0; k < 32; k++) {
            float val = __half2float(s_h[ch][k][col]);
            #pragma unroll
            for (int r = 0; r < 16; r++) {
                int t = k - r;
                if (t >= 0 && t <= 16) acc[r] += wtap(t) * val;
            }
        }

        #pragma unroll
        for (int r = 0; r < 16; r++) {
            int y  = y0 + r;
            int oi = (y * 2048 + px) * 3 + ch;
            float bv = fminf(fmaxf(acc[r], 0.0f), 1.0f) * 255.0f;
            if (mixed) {
                int dyp = 1024 - y;
                if (dxp2 + dyp * dyp < SCLEAN_MAX) bv = img[oi];
            }
            out[oi] = bv;
        }
    }
}

extern "C" void kernel_launch(void* const* d_in, const int* in_sizes, int n_in,
                              void* d_out, int out_size) {
    const float* img;
    const int*   off;
    if (in_sizes[0] == 2048*2048*3) {
        img = (const float*)d_in[0];
        off = (const int*)d_in[1];
    } else {
        img = (const float*)d_in[1];
        off = (const int*)d_in[0];
    }
    float* out = (float*)d_out;

    void* pk = nullptr;
    cudaGetSymbolAddress(&pk, g_packed);
    cudaMemsetAsync(pk, 0, sizeof(unsigned int) * HW, 0);

    dim3 sg((2045 + 255) / 256, 2045);
    k_scatter<<<sg, 256>>>((const int2*)off);

    k_fused<<<dim3(32, 128), 256>>>(img, out);
}

// round 12
// speedup vs baseline: 2.0409x; 1.1712x over previous
#include <cuda_runtime.h>
#include <cuda_fp16.h>

#define HW (2048*2048)
#define SRADII_MAX 589824   // 768^2
#define SCLEAN_MAX 586756   // 766^2
#define RGATE2     585225   // 765^2 : only px with d2>=this can be scatter targets
#define HVWV (2045*2045)

// 32-bit packed winner: (order+1)<<5 | (dh+2)<<3 | (dw+2)<<1 | neg
// src = p + (neg ? -1 : +1) * (dh*2048 + dw).
__device__ unsigned int g_packed[HW];

// Gaussian sigma=2, truncate=4 -> radius 8 ; weight for tap offset o is c_w[|o|]
__constant__ float c_w[9] = {
    0.19947464f, 0.17603575f, 0.12098747f, 0.06475993f,
    0.02699595f, 0.00876430f, 0.00221596f, 0.00043635f, 0.00006692f
};

__device__ __forceinline__ float wtap(int k) {   // k in [0,16], offset k-8
    return c_w[k < 8 ? 8 - k : k - 8];
}

// ---------------------------------------------------------------- smem-tiled scatter
// Block = 64x16 source tile at image coords [X0, X0+TWe) x [Y0, Y0+THe).
// Candidates accumulate in a 67x19 smem tile (halo -2..+1 each dim, since D in [-2,1]).
// Flush: owned cells (writer window inside this tile's source range) -> plain store;
// boundary cells -> global atomicMax (only if candidate exists). No memset needed.
__global__ __launch_bounds__(256) void k_scatter(const int2* __restrict__ off) {
    int X0 = 2 + (blockIdx.x << 6);
    int Y0 = 2 + (blockIdx.y << 4);
    int TWe = min(64, 2047 - X0);
    int THe = min(16, 2047 - Y0);
    int tid = threadIdx.x;

    // Early out: whole source tile inside ring -> no writers (d2 convex, max at corners)
    {
        int dxa = 1024 - X0, dxb = 1024 - (X0 + TWe - 1);
        int dya = 1024 - Y0, dyb = 1024 - (Y0 + THe - 1);
        if (max(dxa*dxa, dxb*dxb) + max(dya*dya, dyb*dyb) < SRADII_MAX) return;
    }

    __shared__ unsigned int s_t[19][67];

    #pragma unroll
    for (int j = 0; j < 5; j++) {
        int i = tid + (j << 8);
        if (i < 19*67) ((unsigned int*)s_t)[i] = 0u;
    }
    __syncthreads();

    #pragma unroll
    for (int j = 0; j < 4; j++) {
        int idx = tid + (j << 8);
        int sy = idx >> 6, sx = idx & 63;
        if (sx >= TWe || sy >= THe) continue;
        int ww = X0 + sx, hh = Y0 + sy;
        int dx = 1024 - ww, dy = 1024 - hh;
        if (dx*dx + dy*dy < SRADII_MAX) continue;

        int local = (hh - 2) * 2045 + (ww - 2);
        int2 o0 = off[local];
        int2 o1 = off[HVWV + local];

        // i=0: own-lin write dominated by i=1's own-lin write; only lin2 needed.
        {
            unsigned o1p1 = (unsigned)(2*local + 1);
            unsigned base = (o1p1 << 5) | ((unsigned)(o0.x + 2) << 3) | ((unsigned)(o0.y + 2) << 1);
            atomicMax(&s_t[sy + 2 + o0.x][sx + 2 + o0.y], base + 32u + 1u);
        }
        // i=1: both writes.
        {
            unsigned o1p1 = (unsigned)(2*HVWV + 2*local + 1);
            unsigned base = (o1p1 << 5) | ((unsigned)(o1.x + 2) << 3) | ((unsigned)(o1.y + 2) << 1);
            atomicMax(&s_t[sy + 2][sx + 2], base);
            atomicMax(&s_t[sy + 2 + o1.x][sx + 2 + o1.y], base + 32u + 1u);
        }
    }
    __syncthreads();

    // Flush 67x19 cells
    #pragma unroll
    for (int j = 0; j < 5; j++) {
        int i = tid + (j << 8);
        if (i >= 19*67) break;
        int cy = i / 67, cx = i - cy * 67;
        int ty = Y0 - 2 + cy, tx = X0 - 2 + cx;
        if (tx < 0 || tx > 2047 || ty < 0 || ty > 2047) continue;
        unsigned val = s_t[cy][cx];
        // ownership: clamped writer window [t-1, t+2] inside this tile's source range
        bool own_x = (max(tx - 1, 2) >= X0) && (min(tx + 2, 2046) <= X0 + TWe - 1);
        bool own_y = (max(ty - 1, 2) >= Y0) && (min(ty + 2, 2046) <= Y0 + THe - 1);
        int g = ty * 2048 + tx;
        if (own_x && own_y) {
            g_packed[g] = val;               // exclusive: plain store (also clears to 0)
        } else if (val) {
            atomicMax(&g_packed[g], val);    // idempotent across replays
        }
    }
}

// ---------------------------------------------------------------- fused gather + H blur + V blur + finalize
// grid (32, 128), block 256. Output tile 64x16, halo 80x32.
// fp16 smem intermediates, fp32 arithmetic. V pass: thread = (column, channel), 16 rows each.
__global__ __launch_bounds__(256, 5) void k_fused(const float* __restrict__ img,
                                                  float* __restrict__ out) {
    int x0 = blockIdx.x << 6;
    int y0 = blockIdx.y << 4;
    int tid = threadIdx.x;

    int dxa = 1024 - x0, dxb = 1024 - (x0 + 63);
    int maxdx2 = max(dxa*dxa, dxb*dxb);
    int mindx2 = (x0 <= 1024 && 1024 <= x0 + 63) ? 0 : min(dxa*dxa, dxb*dxb);
    int dya = 1024 - y0, dyb = 1024 - (y0 + 15);
    int maxdy2 = max(dya*dya, dyb*dyb);
    int mindy2 = (y0 <= 1024 && 1024 <= y0 + 15) ? 0 : min(dya*dya, dyb*dyb);

    if (maxdx2 + maxdy2 < SCLEAN_MAX) {       // whole tile clean: pure float4 copy
        int fb = ((y0 * 2048 + x0) * 3) >> 2;
        const float4* s = (const float4*)img;
        float4*       d = (float4*)out;
        #pragma unroll
        for (int i = 0; i < 3; i++) {
            int j  = tid + (i << 8);
            int row = j / 48, col = j - row * 48;
            int fi = fb + row * 1536 + col;
            d[fi] = s[fi];
        }
        return;
    }

    __shared__ __half s_in[3][32][88];        // gathered /255 (80 valid cols; 88 = 16B-aligned rows)
    __shared__ __half s_h[3][32][66];         // H-blur result (64 valid; 66 rotates banks)

    // ---- load + inline gather (2560 halo pixels, 10 per thread) ----
    const float inv = 1.0f / 255.0f;
    #pragma unroll
    for (int it = 0; it < 10; it++) {
        int i  = tid + (it << 8);
        int hy = i / 80, hx = i - hy * 80;
        int gy = y0 - 8 + hy; gy = gy < 0 ? 0 : (gy > 2047 ? 2047 : gy);
        int gx = x0 - 8 + hx; gx = gx < 0 ? 0 : (gx > 2047 ? 2047 : gx);
        int p  = gy * 2048 + gx;
        int src = p;
        int ddx = 1024 - gx, ddy = 1024 - gy;
        if (ddx*ddx + ddy*ddy >= RGATE2) {
            unsigned v = g_packed[p];
            if (v) {
                int D = (((int)((v >> 3) & 3u)) - 2) * 2048 + (((int)((v >> 1) & 3u)) - 2);
                src = (v & 1u) ? p - D : p + D;
            }
        }
        s_in[0][hy][hx] = __float2half_rn(img[src*3 + 0] * inv);
        s_in[1][hy][hx] = __float2half_rn(img[src*3 + 1] * inv);
        s_in[2][hy][hx] = __float2half_rn(img[src*3 + 2] * inv);
    }
    __syncthreads();

    // ---- H blur: thread = (row yy, col-block xb), 8 outputs per channel ----
    {
        int yy = tid >> 3;
        int xb = (tid & 7) << 3;
        #pragma unroll
        for (int c = 0; c < 3; c++) {
            float v[24];
            const uint4* up = reinterpret_cast<const uint4*>(&s_in[c][yy][xb]);
            #pragma unroll
            for (int q = 0; q < 3; q++) {
                uint4 u = up[q];
                unsigned uw[4] = {u.x, u.y, u.z, u.w};
                #pragma unroll
                for (int m = 0; m < 4; m++) {
                    float2 f = __half22float2(*reinterpret_cast<__half2*>(&uw[m]));
                    v[8*q + 2*m]     = f.x;
                    v[8*q + 2*m + 1] = f.y;
                }
            }
            float ho[8];
            #pragma unroll
            for (int j = 0; j < 8; j++) {
                float a = 0.0f;
                #pragma unroll
                for (int k = 0; k < 17; k++) a += wtap(k) * v[j + k];
                ho[j] = a;
            }
            #pragma unroll
            for (int q = 0; q < 4; q++)
                *reinterpret_cast<__half2*>(&s_h[c][yy][xb + 2*q]) =
                    __floats2half2_rn(ho[2*q], ho[2*q + 1]);
        }
    }
    __syncthreads();

    // ---- V blur: thread = (column, channel); 32 input rows -> 16 output rows ----
    if (tid < 192) {
        int col = tid & 63;
        int ch  = tid >> 6;
        int px  = x0 + col;
        int dxp2 = (1024 - px) * (1024 - px);
        bool mixed = (mindx2 + mindy2) < SCLEAN_MAX;

        float acc[16];
        #pragma unroll
        for (int r = 0; r < 16; r++) acc[r] = 0.0f;

        #pragma unroll
        for (int k = 0; k < 32; k++) {
            float val = __half2float(s_h[ch][k][col]);
            #pragma unroll
            for (int r = 0; r < 16; r++) {
                int t = k - r;
                if (t >= 0 && t <= 16) acc[r] += wtap(t) * val;
            }
        }

        #pragma unroll
        for (int r = 0; r < 16; r++) {
            int y  = y0 + r;
            int oi = (y * 2048 + px) * 3 + ch;
            float bv = fminf(fmaxf(acc[r], 0.0f), 1.0f) * 255.0f;
            if (mixed) {
                int dyp = 1024 - y;
                if (dxp2 + dyp * dyp < SCLEAN_MAX) bv = img[oi];
            }
            out[oi] = bv;
        }
    }
}

extern "C" void kernel_launch(void* const* d_in, const int* in_sizes, int n_in,
                              void* d_out, int out_size) {
    const float* img;
    const int*   off;
    if (in_sizes[0] == 2048*2048*3) {
        img = (const float*)d_in[0];
        off = (const int*)d_in[1];
    } else {
        img = (const float*)d_in[1];
        off = (const int*)d_in[0];
    }
    float* out = (float*)d_out;

    k_scatter<<<dim3(32, 128), 256>>>((const int2*)off);

    k_fused<<<dim3(32, 128), 256>>>(img, out);
}